// round 6
// baseline (speedup 1.0000x reference)
#include <cuda_runtime.h>
#include <math.h>

// Cox partial likelihood, chunk-sorted (v6):
//   32 chunks of 512 sorted by packed (key(T)<<32|idx) via warp-shuffle bitonic
//   (double-buffered SMEM only for stride>=32); e=exp(theta) gathered post-sort;
//   per-chunk suffix sums via shuffle scan. rank: both-sides-sorted SMEM binary
//   searches; partial rss accumulated atomically; LAST rank CTA computes loss.

#define NN     16384
#define TILE   512
#define NCH    32
#define GROUPS 8
#define CPG    (NCH / GROUPS)   // 4
#define NRANK  (NCH * GROUPS)   // 256

typedef unsigned long long ull;

__device__ unsigned g_u  [NCH * TILE];        // sorted keys
__device__ float    g_sfx[NCH * (TILE + 1)];  // suffix sums (+0 sentinel)
__device__ int      g_idx[NCH * TILE];        // original index per sorted slot
__device__ float    g_rss[NN];                // accumulated risk-set sums
__device__ unsigned g_done;                   // rank completion ticket

__device__ __forceinline__ unsigned key_of(float t) {
    unsigned b = __float_as_uint(t);
    return b ^ ((unsigned)((int)b >> 31) | 0x80000000u);
}

__global__ void __launch_bounds__(TILE)
sort_kernel(const float* __restrict__ theta, const float* __restrict__ T, int n) {
    const int c    = blockIdx.x;
    const int t    = threadIdx.x;
    const int lane = t & 31;
    const int w    = t >> 5;
    const int j    = c * TILE + t;

    // zero rss accumulators for this run (rank launches after us)
    g_rss[c * TILE + t] = 0.0f;

    ull kv = (j < n) ? (((ull)key_of(T[j]) << 32) | (unsigned)j) : 0ull;

    __shared__ ull   sbuf[2][TILE];
    __shared__ float swarp[TILE / 32];
    __shared__ float soff [TILE / 32];
    int buf = 0;

    // Bitonic sort ascending
    for (int k = 2; k <= TILE; k <<= 1) {
        for (int s = k >> 1; s > 0; s >>= 1) {
            const bool keep_min = (((t & s) == 0) == ((t & k) == 0));
            ull pkv;
            if (s >= 32) {
                sbuf[buf][t] = kv;
                __syncthreads();
                pkv = sbuf[buf][t ^ s];
                buf ^= 1;                    // next SMEM substage uses other buffer
            } else {
                pkv = __shfl_xor_sync(0xFFFFFFFFu, kv, s);
            }
            const bool take = keep_min ? (pkv < kv) : (pkv > kv);
            if (take) kv = pkv;
        }
    }

    const unsigned u   = (unsigned)(kv >> 32);
    const int      idx = (int)(unsigned)kv;
    const float    e   = (idx < n) ? expf(theta[idx]) : 0.0f;

    // Inclusive suffix sum of e over sorted positions
    float ssum = e;
#pragma unroll
    for (int off = 1; off < 32; off <<= 1) {
        float v = __shfl_down_sync(0xFFFFFFFFu, ssum, off);
        if (lane + off < 32) ssum += v;
    }
    if (lane == 0) swarp[w] = ssum;
    __syncthreads();
    if (t < TILE / 32) {
        float v = swarp[t];
#pragma unroll
        for (int off = 1; off < TILE / 32; off <<= 1) {
            float x = __shfl_down_sync(0xFFFFu, v, off);
            if (t + off < TILE / 32) v += x;
        }
        soff[t] = v - swarp[t];
    }
    __syncthreads();

    g_u  [c * TILE + t]       = u;
    g_sfx[c * (TILE + 1) + t] = ssum + soff[w];
    g_idx[c * TILE + t]       = idx;
    if (t == 0) g_sfx[c * (TILE + 1) + TILE] = 0.0f;
}

__global__ void __launch_bounds__(TILE)
rank_kernel(const float* __restrict__ theta, const float* __restrict__ ev,
            int n, float* __restrict__ out) {
    const int tile = blockIdx.x / GROUPS;
    const int grp  = blockIdx.x % GROUPS;
    const int t    = threadIdx.x;

    __shared__ unsigned ck[CPG][TILE];
    __shared__ float    cs[CPG][TILE + 1];
    __shared__ unsigned sticket;
    __shared__ float    wsum[TILE / 32];

    const unsigned u = g_u[tile * TILE + t];
#pragma unroll
    for (int q = 0; q < CPG; q++) {
        const int c = grp * CPG + q;
        ck[q][t] = g_u[c * TILE + t];
        cs[q][t] = g_sfx[c * (TILE + 1) + t];
        if (t == 0) cs[q][TILE] = 0.0f;
    }
    __syncthreads();

    int lo[CPG];
#pragma unroll
    for (int q = 0; q < CPG; q++) lo[q] = 0;
#pragma unroll
    for (int s = TILE / 2; s > 0; s >>= 1) {
#pragma unroll
        for (int q = 0; q < CPG; q++)
            if (ck[q][lo[q] + s - 1] < u) lo[q] += s;
    }

    float acc = 0.0f;
#pragma unroll
    for (int q = 0; q < CPG; q++) acc += cs[q][lo[q]];

    atomicAdd(&g_rss[tile * TILE + t], acc);

    // Completion ticket: last CTA computes the loss.
    __threadfence();
    __syncthreads();
    if (t == 0) sticket = atomicAdd(&g_done, 1u);
    __syncthreads();
    if (sticket != NRANK - 1) return;

    // --- last CTA: all g_rss finalized & visible ---
    float local = 0.0f;
#pragma unroll
    for (int r = 0; r < NN / TILE; r++) {
        const int s  = r * TILE + t;
        const int io = g_idx[s];
        local += (theta[io] - logf(g_rss[s])) * ev[io];
    }

    for (int off = 16; off > 0; off >>= 1)
        local += __shfl_down_sync(0xFFFFFFFFu, local, off);
    const int lane = t & 31, warp = t >> 5;
    if (lane == 0) wsum[warp] = local;
    __syncthreads();
    if (t == 0) {
        float ssum = 0.0f;
#pragma unroll
        for (int w2 = 0; w2 < TILE / 32; w2++) ssum += wsum[w2];
        out[0] = -ssum / (float)n;
        g_done = 0;                       // reset for next graph replay
    }
}

extern "C" void kernel_launch(void* const* d_in, const int* in_sizes, int n_in,
                              void* d_out, int out_size) {
    const float* theta = (const float*)d_in[0];
    const float* T     = (const float*)d_in[1];
    const float* ev    = (const float*)d_in[2];
    float*       out   = (float*)d_out;
    const int n = in_sizes[0];

    sort_kernel<<<NCH, TILE>>>(theta, T, n);
    rank_kernel<<<NRANK, TILE>>>(theta, ev, n, out);
}

// round 7
// speedup vs baseline: 1.3907x; 1.3907x over previous
#include <cuda_runtime.h>
#include <math.h>

// Cox partial likelihood, chunk-sorted (v7 = v6 sort + v5 rank/loss):
//   32 chunks of 512 sorted by packed (key(T)<<32|idx) via warp-shuffle bitonic
//   (single-barrier double-buffered SMEM for stride>=32); e=exp(theta) gathered
//   post-sort; per-chunk suffix sums via shuffle scan.
//   rank: both-sides-sorted SMEM binary searches -> plain partial stores.
//   loss: sum partials, gather theta/ev via idx, block-reduce, atomicAdd.

#define NN     16384
#define TILE   512
#define NCH    32
#define GROUPS 8
#define CPG    (NCH / GROUPS)   // 4

typedef unsigned long long ull;

__device__ unsigned g_u  [NCH * TILE];        // sorted keys
__device__ float    g_sfx[NCH * (TILE + 1)];  // suffix sums (+0 sentinel)
__device__ int      g_idx[NCH * TILE];        // original index per sorted slot
__device__ float    g_part[GROUPS * NN];      // per-group partial rss

__device__ __forceinline__ unsigned key_of(float t) {
    unsigned b = __float_as_uint(t);
    return b ^ ((unsigned)((int)b >> 31) | 0x80000000u);
}

__global__ void __launch_bounds__(TILE)
sort_kernel(const float* __restrict__ theta, const float* __restrict__ T,
            int n, float* __restrict__ out) {
    const int c    = blockIdx.x;
    const int t    = threadIdx.x;
    const int lane = t & 31;
    const int w    = t >> 5;
    const int j    = c * TILE + t;

    ull kv = (j < n) ? (((ull)key_of(T[j]) << 32) | (unsigned)j) : 0ull;

    __shared__ ull   sbuf[2][TILE];
    __shared__ float swarp[TILE / 32];
    __shared__ float soff [TILE / 32];
    int buf = 0;

    // Bitonic sort ascending
    for (int k = 2; k <= TILE; k <<= 1) {
        for (int s = k >> 1; s > 0; s >>= 1) {
            const bool keep_min = (((t & s) == 0) == ((t & k) == 0));
            ull pkv;
            if (s >= 32) {
                sbuf[buf][t] = kv;
                __syncthreads();
                pkv = sbuf[buf][t ^ s];
                buf ^= 1;                 // next SMEM substage uses other buffer
            } else {
                pkv = __shfl_xor_sync(0xFFFFFFFFu, kv, s);
            }
            const bool take = keep_min ? (pkv < kv) : (pkv > kv);
            if (take) kv = pkv;
        }
    }

    const unsigned u   = (unsigned)(kv >> 32);
    const int      idx = (int)(unsigned)kv;
    const float    e   = (idx < n) ? expf(theta[idx]) : 0.0f;

    // Inclusive suffix sum of e over sorted positions
    float ssum = e;
#pragma unroll
    for (int off = 1; off < 32; off <<= 1) {
        float v = __shfl_down_sync(0xFFFFFFFFu, ssum, off);
        if (lane + off < 32) ssum += v;
    }
    if (lane == 0) swarp[w] = ssum;
    __syncthreads();
    if (t < TILE / 32) {
        float v = swarp[t];
#pragma unroll
        for (int off = 1; off < TILE / 32; off <<= 1) {
            float x = __shfl_down_sync(0xFFFFu, v, off);
            if (t + off < TILE / 32) v += x;
        }
        soff[t] = v - swarp[t];
    }
    __syncthreads();

    g_u  [c * TILE + t]       = u;
    g_sfx[c * (TILE + 1) + t] = ssum + soff[w];
    g_idx[c * TILE + t]       = idx;
    if (t == 0) {
        g_sfx[c * (TILE + 1) + TILE] = 0.0f;
        if (c == 0) out[0] = 0.0f;        // stream-ordered before loss_kernel
    }
}

__global__ void __launch_bounds__(TILE)
rank_kernel() {
    const int tile = blockIdx.x / GROUPS;
    const int grp  = blockIdx.x % GROUPS;
    const int t    = threadIdx.x;

    __shared__ unsigned ck[CPG][TILE];
    __shared__ float    cs[CPG][TILE + 1];

    const unsigned u = g_u[tile * TILE + t];
#pragma unroll
    for (int q = 0; q < CPG; q++) {
        const int c = grp * CPG + q;
        ck[q][t] = g_u[c * TILE + t];
        cs[q][t] = g_sfx[c * (TILE + 1) + t];
        if (t == 0) cs[q][TILE] = 0.0f;
    }
    __syncthreads();

    int lo[CPG];
#pragma unroll
    for (int q = 0; q < CPG; q++) lo[q] = 0;
#pragma unroll
    for (int s = TILE / 2; s > 0; s >>= 1) {
#pragma unroll
        for (int q = 0; q < CPG; q++)
            if (ck[q][lo[q] + s - 1] < u) lo[q] += s;
    }

    float acc = 0.0f;
#pragma unroll
    for (int q = 0; q < CPG; q++) acc += cs[q][lo[q]];

    g_part[grp * NN + tile * TILE + t] = acc;
}

__global__ void __launch_bounds__(TILE)
loss_kernel(const float* __restrict__ theta, const float* __restrict__ ev,
            int n, float* __restrict__ out) {
    const int s = blockIdx.x * TILE + threadIdx.x;

    float term = 0.0f;
    if (s < n) {
        float rss = 0.0f;
#pragma unroll
        for (int g = 0; g < GROUPS; g++) rss += g_part[g * NN + s];
        const int io = g_idx[s];
        term = (theta[io] - logf(rss)) * ev[io];
    }

    for (int off = 16; off > 0; off >>= 1)
        term += __shfl_down_sync(0xFFFFFFFFu, term, off);

    __shared__ float wsum[TILE / 32];
    const int lane = threadIdx.x & 31, warp = threadIdx.x >> 5;
    if (lane == 0) wsum[warp] = term;
    __syncthreads();
    if (threadIdx.x == 0) {
        float ssum = 0.0f;
#pragma unroll
        for (int w = 0; w < TILE / 32; w++) ssum += wsum[w];
        atomicAdd(out, -ssum / (float)n);
    }
}

extern "C" void kernel_launch(void* const* d_in, const int* in_sizes, int n_in,
                              void* d_out, int out_size) {
    const float* theta = (const float*)d_in[0];
    const float* T     = (const float*)d_in[1];
    const float* ev    = (const float*)d_in[2];
    float*       out   = (float*)d_out;
    const int n = in_sizes[0];

    sort_kernel<<<NCH, TILE>>>(theta, T, n, out);
    rank_kernel<<<NCH * GROUPS, TILE>>>();
    loss_kernel<<<NCH, TILE>>>(theta, ev, n, out);
}